// round 9
// baseline (speedup 1.0000x reference)
#include <cuda_runtime.h>
#include <cuda_bf16.h>
#include <cstdint>

// Problem constants (from reference setup_inputs)
#define BATCH  4096
#define CWDIM  1024
#define CODES  128     // C
#define BOOK   256     // K
#define DEMB   8       // D

#define THREADS 128
#define ROWS_PB 256    // 2 rows per thread

// ---------------------------------------------------------------------------
// Fused kernel (R7 instruction mix, finer block granularity).
// grid = (BATCH/256, CODES) = (16,128) = 2048 blocks of 128 threads, one c.
// Each thread argmins 2 rows; codebook broadcasts amortized over both.
// score(k) = 0.5*||c_k||^2 - x . c_k  (same argmin as full distance)
// ---------------------------------------------------------------------------
__global__ void __launch_bounds__(THREADS)
vq_fused_kernel(const float* __restrict__ x,
                const float* __restrict__ cb,
                float* __restrict__ cw_embed,
                float* __restrict__ one_hot)
{
    __shared__ float4        s_cb[BOOK * 2];     // codebook[c]: 256 x 8 floats
    __shared__ float4        s_h4[BOOK / 4];     // 0.5*||c||^2, 4 k's per float4
    __shared__ unsigned char s_idx[ROWS_PB];     // [rsub][it] layout: rsub*128+it

    const int c  = blockIdx.y;
    const int t  = threadIdx.x;
    const int b0 = blockIdx.x * ROWS_PB;

    // ---- Stage codebook[c] into smem (2 codes per thread) ----
    const float4* cb4 = reinterpret_cast<const float4*>(cb + (size_t)c * BOOK * DEMB);
    #pragma unroll
    for (int kk = t; kk < BOOK; kk += THREADS) {
        float4 r0 = cb4[2 * kk + 0];
        float4 r1 = cb4[2 * kk + 1];
        s_cb[2 * kk + 0] = r0;
        s_cb[2 * kk + 1] = r1;
        float h = 0.5f * (r0.x * r0.x + r0.y * r0.y + r0.z * r0.z + r0.w * r0.w +
                          r1.x * r1.x + r1.y * r1.y + r1.z * r1.z + r1.w * r1.w);
        reinterpret_cast<float*>(s_h4)[kk] = h;
    }

    // ---- Load x for this thread's 2 rows: b0+t and b0+128+t ----
    const float4* xpA = reinterpret_cast<const float4*>(x + (size_t)(b0 + t)       * CWDIM + c * DEMB);
    const float4* xpB = reinterpret_cast<const float4*>(x + (size_t)(b0 + 128 + t) * CWDIM + c * DEMB);
    float4 a0 = xpA[0], a1 = xpA[1];
    float4 e0 = xpB[0], e1 = xpB[1];
    const float an0 = -a0.x, an1 = -a0.y, an2 = -a0.z, an3 = -a0.w;
    const float an4 = -a1.x, an5 = -a1.y, an6 = -a1.z, an7 = -a1.w;
    const float bn0 = -e0.x, bn1 = -e0.y, bn2 = -e0.z, bn3 = -e0.w;
    const float bn4 = -e1.x, bn5 = -e1.y, bn6 = -e1.z, bn7 = -e1.w;

    __syncthreads();

    // ---- Argmin over K=256 for both rows, 4 k's per outer iter ----
    float bestA = 3.4e38f, bestB = 3.4e38f;
    int   biA = 0, biB = 0;

    #pragma unroll 2
    for (int kq = 0; kq < BOOK / 4; ++kq) {
        const float4 h4 = s_h4[kq];
        const float hh[4] = {h4.x, h4.y, h4.z, h4.w};
        #pragma unroll
        for (int j = 0; j < 4; ++j) {
            const int k = kq * 4 + j;
            float4 c0 = s_cb[2 * k + 0];
            float4 c1 = s_cb[2 * k + 1];
            float sA = hh[j], sB = hh[j];
            sA = fmaf(an0, c0.x, sA);  sB = fmaf(bn0, c0.x, sB);
            sA = fmaf(an1, c0.y, sA);  sB = fmaf(bn1, c0.y, sB);
            sA = fmaf(an2, c0.z, sA);  sB = fmaf(bn2, c0.z, sB);
            sA = fmaf(an3, c0.w, sA);  sB = fmaf(bn3, c0.w, sB);
            sA = fmaf(an4, c1.x, sA);  sB = fmaf(bn4, c1.x, sB);
            sA = fmaf(an5, c1.y, sA);  sB = fmaf(bn5, c1.y, sB);
            sA = fmaf(an6, c1.z, sA);  sB = fmaf(bn6, c1.z, sB);
            sA = fmaf(an7, c1.w, sA);  sB = fmaf(bn7, c1.w, sB);
            // strict < keeps FIRST minimum (matches jnp.argmin tie-break)
            if (sA < bestA) { bestA = sA; biA = k; }
            if (sB < bestB) { bestB = sB; biB = k; }
        }
    }

    // s_idx layout: [rsub][it] with it = local row index within the 128-row half.
    // Row (b0 + r): r < 128 -> rsub 0, it = r; r >= 128 -> rsub 1, it = r-128.
    s_idx[t]       = (unsigned char)biA;    // rsub 0, it = t
    s_idx[128 + t] = (unsigned char)biB;    // rsub 1, it = t

    // ---- cw_embed for both rows ----
    {
        float4* oA = reinterpret_cast<float4*>(cw_embed + (size_t)(b0 + t)       * CWDIM + c * DEMB);
        oA[0] = s_cb[2 * biA + 0];
        oA[1] = s_cb[2 * biA + 1];
        float4* oB = reinterpret_cast<float4*>(cw_embed + (size_t)(b0 + 128 + t) * CWDIM + c * DEMB);
        oB[0] = s_cb[2 * biB + 0];
        oB[1] = s_cb[2 * biB + 1];
    }

    __syncthreads();

    // ---- one_hot drain: 256 rows x 64 float4, coalesced STG.128.
    // 128 threads -> 2 rows per iteration, 128 iterations.
    // Thread (off = t&63, rsub = t>>6) writes slot off of rows
    //   b0 + rsub*128 + it   (it = 0..127)   <- matches s_idx[rsub*128 + it]
    // Indices prefetched 4-at-a-time via one 32-bit smem load.
    const int off  = t & 63;
    const int rsub = t >> 6;
    const unsigned kb = (unsigned)off * 4u;

    float4* oh4 = reinterpret_cast<float4*>(one_hot)
                + (size_t)(b0 + rsub * 128) * (CODES * BOOK / 4)
                + (size_t)c * (BOOK / 4)
                + off;
    const size_t step4 = (size_t)(CODES * BOOK / 4);   // 1 b-row per iteration

    const unsigned* idx32 = reinterpret_cast<const unsigned*>(s_idx) + rsub * 32;

    #pragma unroll 4
    for (int q = 0; q < 32; ++q) {          // 32 quads = 128 iterations
        unsigned packed = idx32[q];
        #pragma unroll
        for (int j = 0; j < 4; ++j) {
            const unsigned idx = (packed >> (8 * j)) & 0xFFu;
            float4 v;
            v.x = (idx == kb + 0u) ? 1.0f : 0.0f;
            v.y = (idx == kb + 1u) ? 1.0f : 0.0f;
            v.z = (idx == kb + 2u) ? 1.0f : 0.0f;
            v.w = (idx == kb + 3u) ? 1.0f : 0.0f;
            *oh4 = v;
            oh4 += step4;
        }
    }
}

// ---------------------------------------------------------------------------
extern "C" void kernel_launch(void* const* d_in, const int* in_sizes, int n_in,
                              void* d_out, int out_size)
{
    const float* x  = (const float*)d_in[0];   // [4096, 1024]
    const float* cb = (const float*)d_in[1];   // [128, 256, 8]

    float* cw_embed = (float*)d_out;                               // [4096, 1024]
    float* one_hot  = (float*)d_out + (size_t)BATCH * CWDIM;       // [4096, 128, 256]

    dim3 grid(BATCH / ROWS_PB, CODES);                             // (16, 128)
    vq_fused_kernel<<<grid, THREADS>>>(x, cb, cw_embed, one_hot);
}

// round 10
// speedup vs baseline: 1.4528x; 1.4528x over previous
#include <cuda_runtime.h>
#include <cuda_bf16.h>
#include <cstdint>

// Problem constants (from reference setup_inputs)
#define BATCH  4096
#define CWDIM  1024
#define CODES  128     // C
#define BOOK   256     // K
#define DEMB   8       // D

#define THREADS 256
#define ROWS_PB 512    // 2 rows per thread

// ---- 256-bit global ld/st (sm_100+) ----
struct f8 { float v[8]; };

static __device__ __forceinline__ f8 ldg_v8(const float* p) {
    f8 r;
    asm volatile("ld.global.nc.v8.f32 {%0,%1,%2,%3,%4,%5,%6,%7}, [%8];"
                 : "=f"(r.v[0]), "=f"(r.v[1]), "=f"(r.v[2]), "=f"(r.v[3]),
                   "=f"(r.v[4]), "=f"(r.v[5]), "=f"(r.v[6]), "=f"(r.v[7])
                 : "l"(p));
    return r;
}

static __device__ __forceinline__ void stg_v8(float* p, const f8& r) {
    asm volatile("st.global.v8.f32 [%0], {%1,%2,%3,%4,%5,%6,%7,%8};"
                 :: "l"(p),
                    "f"(r.v[0]), "f"(r.v[1]), "f"(r.v[2]), "f"(r.v[3]),
                    "f"(r.v[4]), "f"(r.v[5]), "f"(r.v[6]), "f"(r.v[7])
                 : "memory");
}

// ---------------------------------------------------------------------------
// Fused kernel (R7 structure + 256-bit global accesses).
// grid = (BATCH/512, CODES) = (8,128), block = 256 threads, one c per block.
// Each thread argmins 2 rows; codebook broadcasts amortized over both.
// score(k) = 0.5*||c_k||^2 - x . c_k  (same argmin as full distance)
// ---------------------------------------------------------------------------
__global__ void __launch_bounds__(THREADS)
vq_fused_kernel(const float* __restrict__ x,
                const float* __restrict__ cb,
                float* __restrict__ cw_embed,
                float* __restrict__ one_hot)
{
    __shared__ float4        s_cb[BOOK * 2];     // codebook[c]: 256 x 8 floats
    __shared__ float4        s_h4[BOOK / 4];     // 0.5*||c||^2, 4 k's per float4
    __shared__ unsigned char s_idx[ROWS_PB];     // argmin index per local row

    const int c  = blockIdx.y;
    const int t  = threadIdx.x;
    const int b0 = blockIdx.x * ROWS_PB;

    // ---- Stage codebook[c] into smem (1 code per thread) ----
    const float4* cb4 = reinterpret_cast<const float4*>(cb + (size_t)c * BOOK * DEMB);
    {
        float4 r0 = cb4[t * 2 + 0];
        float4 r1 = cb4[t * 2 + 1];
        s_cb[t * 2 + 0] = r0;
        s_cb[t * 2 + 1] = r1;
        float h = 0.5f * (r0.x * r0.x + r0.y * r0.y + r0.z * r0.z + r0.w * r0.w +
                          r1.x * r1.x + r1.y * r1.y + r1.z * r1.z + r1.w * r1.w);
        reinterpret_cast<float*>(s_h4)[t] = h;
    }

    // ---- Load x for this thread's 2 rows (one 32B load per row) ----
    f8 xa = ldg_v8(x + (size_t)(b0 + t)       * CWDIM + c * DEMB);
    f8 xb = ldg_v8(x + (size_t)(b0 + 256 + t) * CWDIM + c * DEMB);
    const float an0 = -xa.v[0], an1 = -xa.v[1], an2 = -xa.v[2], an3 = -xa.v[3];
    const float an4 = -xa.v[4], an5 = -xa.v[5], an6 = -xa.v[6], an7 = -xa.v[7];
    const float bn0 = -xb.v[0], bn1 = -xb.v[1], bn2 = -xb.v[2], bn3 = -xb.v[3];
    const float bn4 = -xb.v[4], bn5 = -xb.v[5], bn6 = -xb.v[6], bn7 = -xb.v[7];

    __syncthreads();

    // ---- Argmin over K=256 for both rows, 4 k's per outer iter ----
    float bestA = 3.4e38f, bestB = 3.4e38f;
    int   biA = 0, biB = 0;

    #pragma unroll 2
    for (int kq = 0; kq < BOOK / 4; ++kq) {
        const float4 h4 = s_h4[kq];
        const float hh[4] = {h4.x, h4.y, h4.z, h4.w};
        #pragma unroll
        for (int j = 0; j < 4; ++j) {
            const int k = kq * 4 + j;
            float4 c0 = s_cb[2 * k + 0];
            float4 c1 = s_cb[2 * k + 1];
            float sA = hh[j], sB = hh[j];
            sA = fmaf(an0, c0.x, sA);  sB = fmaf(bn0, c0.x, sB);
            sA = fmaf(an1, c0.y, sA);  sB = fmaf(bn1, c0.y, sB);
            sA = fmaf(an2, c0.z, sA);  sB = fmaf(bn2, c0.z, sB);
            sA = fmaf(an3, c0.w, sA);  sB = fmaf(bn3, c0.w, sB);
            sA = fmaf(an4, c1.x, sA);  sB = fmaf(bn4, c1.x, sB);
            sA = fmaf(an5, c1.y, sA);  sB = fmaf(bn5, c1.y, sB);
            sA = fmaf(an6, c1.z, sA);  sB = fmaf(bn6, c1.z, sB);
            sA = fmaf(an7, c1.w, sA);  sB = fmaf(bn7, c1.w, sB);
            // strict < keeps FIRST minimum (matches jnp.argmin tie-break)
            if (sA < bestA) { bestA = sA; biA = k; }
            if (sB < bestB) { bestB = sB; biB = k; }
        }
    }

    s_idx[t]       = (unsigned char)biA;
    s_idx[t + 256] = (unsigned char)biB;

    // ---- cw_embed for both rows (one 32B store per row) ----
    {
        float4 pA0 = s_cb[2 * biA + 0], pA1 = s_cb[2 * biA + 1];
        f8 wa = { pA0.x, pA0.y, pA0.z, pA0.w, pA1.x, pA1.y, pA1.z, pA1.w };
        stg_v8(cw_embed + (size_t)(b0 + t) * CWDIM + c * DEMB, wa);

        float4 pB0 = s_cb[2 * biB + 0], pB1 = s_cb[2 * biB + 1];
        f8 wb = { pB0.x, pB0.y, pB0.z, pB0.w, pB1.x, pB1.y, pB1.z, pB1.w };
        stg_v8(cw_embed + (size_t)(b0 + 256 + t) * CWDIM + c * DEMB, wb);
    }

    __syncthreads();

    // ---- one_hot drain: 512 rows x 256 floats. 32 threads cover one full
    // 1KB row per warp-instruction (8 floats = 32B per thread).
    // 256 threads -> 8 rows per iteration, 64 iterations, STG.256.
    const int off  = t & 31;    // 8-float slot within row (k = off*8 .. off*8+7)
    const int rsub = t >> 5;    // row within group of 8
    const unsigned kb = (unsigned)off * 8u;

    float* ohp = one_hot
               + (size_t)(b0 + rsub) * (CODES * BOOK)
               + (size_t)c * BOOK
               + (size_t)off * 8;
    const size_t step = (size_t)8 * (CODES * BOOK);   // 8 b-rows per iteration

    #pragma unroll 4
    for (int it = 0; it < ROWS_PB / 8; ++it) {
        const unsigned idx = s_idx[it * 8 + rsub];
        f8 v;
        #pragma unroll
        for (int j = 0; j < 8; ++j)
            v.v[j] = (idx == kb + (unsigned)j) ? 1.0f : 0.0f;
        stg_v8(ohp, v);
        ohp += step;
    }
}

// ---------------------------------------------------------------------------
extern "C" void kernel_launch(void* const* d_in, const int* in_sizes, int n_in,
                              void* d_out, int out_size)
{
    const float* x  = (const float*)d_in[0];   // [4096, 1024]
    const float* cb = (const float*)d_in[1];   // [128, 256, 8]

    float* cw_embed = (float*)d_out;                               // [4096, 1024]
    float* one_hot  = (float*)d_out + (size_t)BATCH * CWDIM;       // [4096, 128, 256]

    dim3 grid(BATCH / ROWS_PB, CODES);                             // (8, 128)
    vq_fused_kernel<<<grid, THREADS>>>(x, cb, cw_embed, one_hot);
}

// round 11
// speedup vs baseline: 1.4942x; 1.0285x over previous
#include <cuda_runtime.h>
#include <cuda_bf16.h>
#include <cstdint>

// Problem constants (from reference setup_inputs)
#define BATCH  4096
#define CWDIM  1024
#define CODES  128     // C
#define BOOK   256     // K
#define DEMB   8       // D

#define THREADS 256
#define ROWS_PB 512    // 2 rows per thread

// ---- 256-bit global ld/st (sm_100+) ----
struct f8 { float v[8]; };

static __device__ __forceinline__ f8 ldg_v8(const float* p) {
    f8 r;
    asm volatile("ld.global.nc.v8.f32 {%0,%1,%2,%3,%4,%5,%6,%7}, [%8];"
                 : "=f"(r.v[0]), "=f"(r.v[1]), "=f"(r.v[2]), "=f"(r.v[3]),
                   "=f"(r.v[4]), "=f"(r.v[5]), "=f"(r.v[6]), "=f"(r.v[7])
                 : "l"(p));
    return r;
}

static __device__ __forceinline__ void stg_v8(float* p, const f8& r) {
    asm volatile("st.global.v8.f32 [%0], {%1,%2,%3,%4,%5,%6,%7,%8};"
                 :: "l"(p),
                    "f"(r.v[0]), "f"(r.v[1]), "f"(r.v[2]), "f"(r.v[3]),
                    "f"(r.v[4]), "f"(r.v[5]), "f"(r.v[6]), "f"(r.v[7])
                 : "memory");
}

// ---- packed fp32x2 (sm_103a native) ----
#define FMA2(acc, a, b) \
    asm("fma.rn.f32x2 %0, %1, %2, %0;" : "+l"(acc) : "l"(a), "l"(b))
#define UNPACK2(lo, hi, v) \
    asm("mov.b64 {%0, %1}, %2;" : "=f"(lo), "=f"(hi) : "l"(v))

static __device__ __forceinline__ unsigned long long pack2f(float a, float b) {
    unsigned long long r;
    asm("mov.b64 %0, {%1, %2};" : "=l"(r) : "f"(a), "f"(b));
    return r;
}

// ---------------------------------------------------------------------------
// Fused kernel: R10 structure + k-pair-packed f32x2 argmin.
// grid = (BATCH/512, CODES) = (8,128), block = 256, one c per block.
// Codebook stored k-pair interleaved: s_pk[kp*8+d] = (cb[2kp][d], cb[2kp+1][d]).
// Accumulator lane pair = scores of codes (2kp, 2kp+1) for one row.
// score(k) = 0.5*||c_k||^2 - x . c_k  (same argmin as full distance)
// ---------------------------------------------------------------------------
__global__ void __launch_bounds__(THREADS)
vq_fused_kernel(const float* __restrict__ x,
                const float* __restrict__ cb,
                float* __restrict__ cw_embed,
                float* __restrict__ one_hot)
{
    __shared__ float4             s_cb[BOOK * 2];          // 8 KB plain (gather)
    __shared__ unsigned long long s_pk[(BOOK / 2) * 8];    // 8 KB k-pair interleaved
    __shared__ unsigned long long s_hp[BOOK / 2];          // 1 KB (h_k0, h_k1) pairs
    __shared__ unsigned char      s_idx[ROWS_PB];

    const int c  = blockIdx.y;
    const int t  = threadIdx.x;
    const int b0 = blockIdx.x * ROWS_PB;

    // ---- Stage codebook[c]: thread t handles code k = t ----
    const float4* cb4 = reinterpret_cast<const float4*>(cb + (size_t)c * BOOK * DEMB);
    {
        float4 r0 = cb4[t * 2 + 0];
        float4 r1 = cb4[t * 2 + 1];
        s_cb[t * 2 + 0] = r0;
        s_cb[t * 2 + 1] = r1;
        float h = 0.5f * (r0.x * r0.x + r0.y * r0.y + r0.z * r0.z + r0.w * r0.w +
                          r1.x * r1.x + r1.y * r1.y + r1.z * r1.z + r1.w * r1.w);
        const int kp   = t >> 1;
        const int lane = t & 1;
        unsigned* pk32 = reinterpret_cast<unsigned*>(s_pk);
        const float vals[8] = {r0.x, r0.y, r0.z, r0.w, r1.x, r1.y, r1.z, r1.w};
        #pragma unroll
        for (int d = 0; d < 8; ++d)
            pk32[(kp * 8 + d) * 2 + lane] = __float_as_uint(vals[d]);
        reinterpret_cast<unsigned*>(s_hp)[kp * 2 + lane] = __float_as_uint(h);
    }

    // ---- Load x for this thread's 2 rows; splat (-x_d, -x_d) once ----
    f8 xa = ldg_v8(x + (size_t)(b0 + t)       * CWDIM + c * DEMB);
    f8 xb = ldg_v8(x + (size_t)(b0 + 256 + t) * CWDIM + c * DEMB);
    unsigned long long xA[8], xB[8];
    #pragma unroll
    for (int d = 0; d < 8; ++d) {
        xA[d] = pack2f(-xa.v[d], -xa.v[d]);
        xB[d] = pack2f(-xb.v[d], -xb.v[d]);
    }

    __syncthreads();

    // ---- Argmin over 128 k-pairs for both rows ----
    float bestA = 3.4e38f, bestB = 3.4e38f;
    int   biA = 0, biB = 0;

    const ulonglong2* pk2 = reinterpret_cast<const ulonglong2*>(s_pk);

    #pragma unroll 2
    for (int kp = 0; kp < BOOK / 2; ++kp) {
        const unsigned long long h = s_hp[kp];
        ulonglong2 q0 = pk2[kp * 4 + 0];
        ulonglong2 q1 = pk2[kp * 4 + 1];
        ulonglong2 q2 = pk2[kp * 4 + 2];
        ulonglong2 q3 = pk2[kp * 4 + 3];

        unsigned long long aA = h, aB = h;
        FMA2(aA, xA[0], q0.x);  FMA2(aB, xB[0], q0.x);
        FMA2(aA, xA[1], q0.y);  FMA2(aB, xB[1], q0.y);
        FMA2(aA, xA[2], q1.x);  FMA2(aB, xB[2], q1.x);
        FMA2(aA, xA[3], q1.y);  FMA2(aB, xB[3], q1.y);
        FMA2(aA, xA[4], q2.x);  FMA2(aB, xB[4], q2.x);
        FMA2(aA, xA[5], q2.y);  FMA2(aB, xB[5], q2.y);
        FMA2(aA, xA[6], q3.x);  FMA2(aB, xB[6], q3.x);
        FMA2(aA, xA[7], q3.y);  FMA2(aB, xB[7], q3.y);

        float sA0, sA1, sB0, sB1;
        UNPACK2(sA0, sA1, aA);
        UNPACK2(sB0, sB1, aB);

        const int k0 = kp * 2, k1 = kp * 2 + 1;
        // strict < in ascending-k order keeps FIRST minimum (jnp.argmin)
        if (sA0 < bestA) { bestA = sA0; biA = k0; }
        if (sA1 < bestA) { bestA = sA1; biA = k1; }
        if (sB0 < bestB) { bestB = sB0; biB = k0; }
        if (sB1 < bestB) { bestB = sB1; biB = k1; }
    }

    s_idx[t]       = (unsigned char)biA;
    s_idx[t + 256] = (unsigned char)biB;

    // ---- cw_embed for both rows (one 32B store per row) ----
    {
        float4 pA0 = s_cb[2 * biA + 0], pA1 = s_cb[2 * biA + 1];
        f8 wa = { pA0.x, pA0.y, pA0.z, pA0.w, pA1.x, pA1.y, pA1.z, pA1.w };
        stg_v8(cw_embed + (size_t)(b0 + t) * CWDIM + c * DEMB, wa);

        float4 pB0 = s_cb[2 * biB + 0], pB1 = s_cb[2 * biB + 1];
        f8 wb = { pB0.x, pB0.y, pB0.z, pB0.w, pB1.x, pB1.y, pB1.z, pB1.w };
        stg_v8(cw_embed + (size_t)(b0 + 256 + t) * CWDIM + c * DEMB, wb);
    }

    __syncthreads();

    // ---- one_hot drain: 512 rows x 256 floats, STG.256 (R10 structure).
    // 32 threads cover one 1KB row per warp-instruction; 8 rows per iter.
    const int off  = t & 31;    // 8-float slot within row
    const int rsub = t >> 5;    // row within group of 8
    const unsigned kb = (unsigned)off * 8u;

    float* ohp = one_hot
               + (size_t)(b0 + rsub) * (CODES * BOOK)
               + (size_t)c * BOOK
               + (size_t)off * 8;
    const size_t step = (size_t)8 * (CODES * BOOK);

    #pragma unroll 4
    for (int it = 0; it < ROWS_PB / 8; ++it) {
        const unsigned idx = s_idx[it * 8 + rsub];
        f8 v;
        #pragma unroll
        for (int j = 0; j < 8; ++j)
            v.v[j] = (idx == kb + (unsigned)j) ? 1.0f : 0.0f;
        stg_v8(ohp, v);
        ohp += step;
    }
}

// ---------------------------------------------------------------------------
extern "C" void kernel_launch(void* const* d_in, const int* in_sizes, int n_in,
                              void* d_out, int out_size)
{
    const float* x  = (const float*)d_in[0];   // [4096, 1024]
    const float* cb = (const float*)d_in[1];   // [128, 256, 8]

    float* cw_embed = (float*)d_out;                               // [4096, 1024]
    float* one_hot  = (float*)d_out + (size_t)BATCH * CWDIM;       // [4096, 128, 256]

    dim3 grid(BATCH / ROWS_PB, CODES);                             // (8, 128)
    vq_fused_kernel<<<grid, THREADS>>>(x, cb, cw_embed, one_hot);
}